// round 14
// baseline (speedup 1.0000x reference)
#include <cuda_runtime.h>
#include <cstdint>

// Problem constants (fixed by setup_inputs)
#define B_   16
#define A_   16
#define T_   14
#define S_   1024
#define S2_  512       // estimated (even) subcarriers
#define SYM0 2
#define SYM1 11

// Expected output: real part only, float32, shape (B, R=1, T, S, A, A)
//   = 58,720,256 floats (verified in R3).
#define FULL_N4 14680064u   // float4 count

// cov[b, s, i, j] = 0.5 * sum_{sym in {2,11}} Re( y[b,i,sym,2*(s>>1)] * conj(y[b,j,sym,2*(s>>1)]) )
// broadcast over t (14 copies); s and s+1 share the tile (closest even sc).
//
// R14 = champion structure with 256-bit stores (sm_100+ STG.256):
//   2048 blocks x 256 threads; block owns FOUR s2 (8 output tiles, 8KB/t).
//   Each thread computes 8 consecutive floats (half a cov row) and issues
//   14 st.global.cs.v8.f32 — address pattern identical to champion, half
//   the store ops / L1tex wavefronts.
__global__ __launch_bounds__(256, 8)
void cov_bcast_v8_kernel(const float* __restrict__ y_real,
                         const float* __restrict__ y_imag,
                         float*       __restrict__ out)
{
    __shared__ float2 sv[4][2][A_];   // [s2_local][pilot][antenna]

    const int bid = blockIdx.x;
    const int b   = bid >> 7;                  // / 128 quads
    const int p   = bid & 127;                 // s2 quad: s2 = 4p .. 4p+3
    const int tid = threadIdx.x;

    // ---- gather: threads 0..127 load 4 s2 x 2 sym x 16 ant complex ----
    if (tid < 128) {
        const int a   = tid & (A_ - 1);
        const int k   = (tid >> 4) & 1;
        const int c   = tid >> 5;              // s2_local 0..3
        const int sym = k ? SYM1 : SYM0;
        const int sc  = 8 * p + 2 * c;         // even subcarrier 2*(4p+c)
        const long off = (((long)(b * A_ + a)) * T_ + sym) * S_ + sc;
        sv[c][k][a] = make_float2(__ldg(y_real + off), __ldg(y_imag + off));
    }
    __syncthreads();

    // ---- compute 8 consecutive floats per thread: cov[i][j0..j0+7] ----
    const int r        = tid & 31;             // chunk within one A*A tile (32 x 32B)
    const int sc_local = tid >> 5;             // 0..7 -> output sc = 8p + sc_local
    const int c        = sc_local >> 1;        // source s2_local 0..3
    const int i        = r >> 1;
    const int j0       = (r & 1) << 3;

    const float2 vi0 = sv[c][0][i];
    const float2 vi1 = sv[c][1][i];

    float v[8];
#pragma unroll
    for (int d = 0; d < 8; ++d) {
        const float2 u = sv[c][0][j0 + d];
        const float2 w = sv[c][1][j0 + d];
        v[d] = 0.5f * (vi0.x * u.x + vi0.y * u.y + vi1.x * w.x + vi1.y * w.y);
    }

    // ---- broadcast: 14 x STG.256 (evict-first), 8KB contiguous per block/t ----
    // float offset: ((b*T + t)*S + 8p + sc_local) * 256 + r*8
    const float* base0 = out + ((size_t)(b * T_) * S_ + 8 * (size_t)p + sc_local) * 256
                             + ((size_t)r << 3);
    const size_t t_stride_bytes = (size_t)S_ * 256 * 4;   // 1 MB per t step

    const char* ptr = (const char*)base0;
#pragma unroll
    for (int t = 0; t < T_; ++t) {
        asm volatile("st.global.cs.v8.f32 [%0], {%1,%2,%3,%4,%5,%6,%7,%8};"
                     :: "l"(ptr),
                        "f"(v[0]), "f"(v[1]), "f"(v[2]), "f"(v[3]),
                        "f"(v[4]), "f"(v[5]), "f"(v[6]), "f"(v[7])
                     : "memory");
        ptr += t_stride_bytes;
    }
}

// ---------------------------------------------------------------------------
// Guarded fallback (champion R9 structure): bounds-checked __stcs. Used only
// if out_size differs from the verified full shape. Cannot fault.
// ---------------------------------------------------------------------------
__global__ __launch_bounds__(256, 8)
void cov_guarded_kernel(const float* __restrict__ y_real,
                        const float* __restrict__ y_imag,
                        float4*      __restrict__ out4,
                        size_t n4)
{
    __shared__ float2 sv[2][2][A_];

    const int bid = blockIdx.x;
    const int b   = bid >> 8;
    const int p   = bid & 255;
    const int tid = threadIdx.x;

    if (tid < 64) {
        const int a   = tid & (A_ - 1);
        const int k   = (tid >> 4) & 1;
        const int c   = tid >> 5;
        const int sym = k ? SYM1 : SYM0;
        const int sc  = 4 * p + 2 * c;
        const long off = (((long)(b * A_ + a)) * T_ + sym) * S_ + sc;
        sv[c][k][a] = make_float2(__ldg(y_real + off), __ldg(y_imag + off));
    }
    __syncthreads();

    const int q        = tid & 63;
    const int sc_local = tid >> 6;
    const int c        = sc_local >> 1;
    const int i        = q >> 2;
    const int j0       = (q & 3) << 2;

    const float2 vi0 = sv[c][0][i];
    const float2 vi1 = sv[c][1][i];

    float4 val;
    {
        float2 u = sv[c][0][j0 + 0], w = sv[c][1][j0 + 0];
        val.x = 0.5f * (vi0.x * u.x + vi0.y * u.y + vi1.x * w.x + vi1.y * w.y);
        u = sv[c][0][j0 + 1]; w = sv[c][1][j0 + 1];
        val.y = 0.5f * (vi0.x * u.x + vi0.y * u.y + vi1.x * w.x + vi1.y * w.y);
        u = sv[c][0][j0 + 2]; w = sv[c][1][j0 + 2];
        val.z = 0.5f * (vi0.x * u.x + vi0.y * u.y + vi1.x * w.x + vi1.y * w.y);
        u = sv[c][0][j0 + 3]; w = sv[c][1][j0 + 3];
        val.w = 0.5f * (vi0.x * u.x + vi0.y * u.y + vi1.x * w.x + vi1.y * w.y);
    }

    size_t idx = ((size_t)(b * T_) * S_ + 4 * (size_t)p + sc_local) * 64 + q;
    const size_t t_stride = (size_t)S_ * 64;

#pragma unroll
    for (int t = 0; t < T_; ++t) {
        if (idx < n4) __stcs(out4 + idx, val);
        idx += t_stride;
    }
}

extern "C" void kernel_launch(void* const* d_in, const int* in_sizes, int n_in,
                              void* d_out, int out_size)
{
    // Identify the two big float arrays (3,670,016 elements each) by size;
    // disambiguate real/imag by input ordering (verified in R3).
    const float* big[2] = {nullptr, nullptr};
    int nbig = 0;
    for (int i = 0; i < n_in; ++i) {
        if (in_sizes[i] > 100000 && nbig < 2) big[nbig++] = (const float*)d_in[i];
    }

    const float* y_real;
    const float* y_imag;
    if (in_sizes[0] > 100000) {
        y_real = big[0]; y_imag = big[1];   // insertion order (verified)
    } else {
        y_imag = big[0]; y_real = big[1];   // alphabetical order
    }

    const size_t n4 = (size_t)out_size / 4;

    if (n4 == (size_t)FULL_N4) {
        cov_bcast_v8_kernel<<<B_ * (S2_ / 4), 256>>>(y_real, y_imag, (float*)d_out);
    } else {
        cov_guarded_kernel<<<B_ * (S2_ / 2), 256>>>(y_real, y_imag,
                                                    (float4*)d_out, n4);
    }
}

// round 15
// speedup vs baseline: 1.1221x; 1.1221x over previous
#include <cuda_runtime.h>
#include <cstdint>

// Problem constants (fixed by setup_inputs)
#define B_   16
#define A_   16
#define T_   14
#define S_   1024
#define S2_  512       // estimated (even) subcarriers
#define SYM0 2
#define SYM1 11

// Expected output: real part only, float32, shape (B, R=1, T, S, A, A)
//   = 58,720,256 floats = 14,680,064 float4 (verified in R3).
#define FULL_N4 14680064u

// cov[b, s, i, j] = 0.5 * sum_{sym in {2,11}} Re( y[b,i,sym,2*(s>>1)] * conj(y[b,j,sym,2*(s>>1)]) )
// broadcast over t (14 copies); s and s+1 share the tile (closest even sc).
//
// FINAL CHAMPION (R9/R13): 4096 blocks x 256 threads. Each block owns an
// s2-pair -> 4 output subcarrier tiles. Threads 0..63 gather the 2x2x16
// complex pilot vectors into smem; each thread computes ONE float4 of the
// real covariance tile; then 14 guard-free evict-first streaming stores
// (4KB contiguous burst per block per t).
//
// Measured: 36.96-37.22us wall across three benches = 6.33 TB/s sustained
// DRAM write stream (~79% of 8TB/s spec) — at the pure-store hardware
// floor. Exhaustively verified optimal across store-op (plain/stcs/stwt/
// policy/TMA/v8), burst-width (2/4/8KB), geometry, L2-policy, and guard
// axes over rounds 3-14; every deviation regressed or was neutral.
template <bool GUARDED>
__global__ __launch_bounds__(256, 8)
void cov_bcast2_kernel(const float* __restrict__ y_real,
                       const float* __restrict__ y_imag,
                       float4*      __restrict__ out4,
                       size_t n4)
{
    __shared__ float2 sv[2][2][A_];   // [s2_local][pilot][antenna]

    const int bid = blockIdx.x;
    const int b   = bid >> 8;                  // batch
    const int p   = bid & 255;                 // s2 pair index: s2 = 2p, 2p+1
    const int tid = threadIdx.x;

    // ---- gather: threads 0..63 load 2 s2 x 2 sym x 16 ant complex ----
    if (tid < 64) {
        const int a   = tid & (A_ - 1);
        const int k   = (tid >> 4) & 1;
        const int c   = tid >> 5;              // s2_local 0/1
        const int sym = k ? SYM1 : SYM0;
        const int sc  = 4 * p + 2 * c;         // even subcarrier 2*(2p+c)
        const long off = (((long)(b * A_ + a)) * T_ + sym) * S_ + sc;
        sv[c][k][a] = make_float2(__ldg(y_real + off), __ldg(y_imag + off));
    }
    __syncthreads();

    // ---- compute ONE float4 (4 adjacent j of real cov) per thread ----
    const int q        = tid & 63;             // float4 within one A*A tile
    const int sc_local = tid >> 6;             // 0..3 -> output sc = 4p + sc_local
    const int c        = sc_local >> 1;        // source s2_local
    const int i        = q >> 2;
    const int j0       = (q & 3) << 2;

    const float2 vi0 = sv[c][0][i];
    const float2 vi1 = sv[c][1][i];

    float4 val;
    {
        float2 u = sv[c][0][j0 + 0], w = sv[c][1][j0 + 0];
        val.x = 0.5f * (vi0.x * u.x + vi0.y * u.y + vi1.x * w.x + vi1.y * w.y);
        u = sv[c][0][j0 + 1]; w = sv[c][1][j0 + 1];
        val.y = 0.5f * (vi0.x * u.x + vi0.y * u.y + vi1.x * w.x + vi1.y * w.y);
        u = sv[c][0][j0 + 2]; w = sv[c][1][j0 + 2];
        val.z = 0.5f * (vi0.x * u.x + vi0.y * u.y + vi1.x * w.x + vi1.y * w.y);
        u = sv[c][0][j0 + 3]; w = sv[c][1][j0 + 3];
        val.w = 0.5f * (vi0.x * u.x + vi0.y * u.y + vi1.x * w.x + vi1.y * w.y);
    }

    // ---- broadcast: 14 streaming stores, 4KB contiguous per block per t ----
    // out float4 index: ((b*T + t)*S + 4p + sc_local) * 64 + q
    size_t idx = ((size_t)(b * T_) * S_ + 4 * (size_t)p + sc_local) * 64 + q;
    const size_t t_stride = (size_t)S_ * 64;

#pragma unroll
    for (int t = 0; t < T_; ++t) {
        if (GUARDED) {
            if (idx < n4) __stcs(out4 + idx, val);
        } else {
            __stcs(out4 + idx, val);           // guard-free pure STG.128 stream
        }
        idx += t_stride;
    }
}

extern "C" void kernel_launch(void* const* d_in, const int* in_sizes, int n_in,
                              void* d_out, int out_size)
{
    // Identify the two big float arrays (3,670,016 elements each) by size;
    // disambiguate real/imag by input ordering (verified in R3).
    const float* big[2] = {nullptr, nullptr};
    int nbig = 0;
    for (int i = 0; i < n_in; ++i) {
        if (in_sizes[i] > 100000 && nbig < 2) big[nbig++] = (const float*)d_in[i];
    }

    const float* y_real;
    const float* y_imag;
    if (in_sizes[0] > 100000) {
        y_real = big[0]; y_imag = big[1];   // insertion order (verified)
    } else {
        y_imag = big[0]; y_real = big[1];   // alphabetical order
    }

    const size_t n4 = (size_t)out_size / 4;

    if (n4 == (size_t)FULL_N4) {
        // Verified full-size output: no per-store bounds checks.
        cov_bcast2_kernel<false><<<B_ * (S2_ / 2), 256>>>(y_real, y_imag,
                                                          (float4*)d_out, n4);
    } else {
        // Unexpected size: guarded variant (cannot fault).
        cov_bcast2_kernel<true><<<B_ * (S2_ / 2), 256>>>(y_real, y_imag,
                                                         (float4*)d_out, n4);
    }
}